// round 5
// baseline (speedup 1.0000x reference)
#include <cuda_runtime.h>
#include <cstdint>

typedef unsigned long long u64;
typedef unsigned int u32;

#define G_DIM 2048
#define T_DIM 16
#define B_DIM 256
#define P_DIM 64

// Scratch (device globals: no allocation allowed)
__device__ u64  g_pv[B_DIM];
__device__ int4 g_T[3 * 17 * 17];   // T[k][a][b] = (1+w^{k+1})^a (1-w^{k+1})^b, a+b<=16

// ---------------------------------------------------------------------------
// Ring multiply in basis (1, w, w^2, w^3), w^4 = -1.
// ---------------------------------------------------------------------------
__device__ __forceinline__ void ringmul(int* z, const int* x, const int* y) {
    z[0] = x[0]*y[0] - x[1]*y[3] - x[2]*y[2] - x[3]*y[1];
    z[1] = x[0]*y[1] + x[1]*y[0] - x[2]*y[3] - x[3]*y[2];
    z[2] = x[0]*y[2] + x[1]*y[1] + x[2]*y[0] - x[3]*y[3];
    z[3] = x[0]*y[3] + x[1]*y[2] + x[2]*y[1] + x[3]*y[0];
}

// ---------------------------------------------------------------------------
// Init kernel. Block 0: build the power tables g_T. Blocks 1..32: pack
// param_vals rows (256 rows x 64 int32 0/1) into u64 bitsets via ballot.
// ---------------------------------------------------------------------------
__global__ void init_kernel(const int* __restrict__ param_vals, u64* __restrict__ pv) {
    if (blockIdx.x == 0) {
        // 867 entries: e = k*289 + a*17 + b
        for (int e = threadIdx.x; e < 3 * 289; e += blockDim.x) {
            int k = e / 289, r = e % 289, a = r / 17, b = r % 17;
            int4 out;
            if (a + b > 16) {
                out = make_int4(0, 0, 0, 0);
            } else {
                int kk = k + 1;                 // rotation 1..3
                int fp[4] = {1, 0, 0, 0};       // 1 + w^kk
                int fm[4] = {1, 0, 0, 0};       // 1 - w^kk
                fp[kk] = 1; fm[kk] = -1;
                int acc[4] = {1, 0, 0, 0}, tmp[4];
                for (int i = 0; i < a; i++) { ringmul(tmp, acc, fp); acc[0]=tmp[0]; acc[1]=tmp[1]; acc[2]=tmp[2]; acc[3]=tmp[3]; }
                for (int i = 0; i < b; i++) { ringmul(tmp, acc, fm); acc[0]=tmp[0]; acc[1]=tmp[1]; acc[2]=tmp[2]; acc[3]=tmp[3]; }
                out = make_int4(acc[0], acc[1], acc[2], acc[3]);
            }
            g_T[e] = out;
        }
    } else {
        int row  = (blockIdx.x - 1) * 8 + (threadIdx.x >> 5);
        int lane = threadIdx.x & 31;
        if (row < B_DIM) {
            const int* base = param_vals + (size_t)row * P_DIM;
            u32 lo = __ballot_sync(0xffffffffu, base[lane] & 1);
            u32 hi = __ballot_sync(0xffffffffu, base[lane + 32] & 1);
            if (lane == 0) pv[row] = ((u64)hi << 32) | (u64)lo;
        }
    }
}

// ---------------------------------------------------------------------------
// Main kernel: one block per g, 256 threads = 256 b's. Branch-free:
//   cp (packed byte counters) += parity_bit * (+-2^{8k}) per term (IMAD),
//   then b_k = byte k of cp; result = T1[b1]*T2[b2]*T3[b3] * sc,
//   sc = (b0==0) ? 2^{m0} : 0.  Output float32 (B,G,4); c3_ref = -z3.
// ---------------------------------------------------------------------------
__global__ void __launch_bounds__(256)
nodephases_main_kernel(const int* __restrict__ params,
                       const int* __restrict__ phases,
                       const int* __restrict__ counts,
                       const u64* __restrict__ pv,
                       float* __restrict__ out) {
    const int g    = blockIdx.x;
    const int tid  = threadIdx.x;
    const int lane = tid & 31;
    const int warp = tid >> 5;

    __shared__ int4 s_term[T_DIM];   // x = w_lo, y = w_hi, z = pw (+-2^{8k} or 0), w unused
    __shared__ int4 s_T[3 * 17];     // staged table rows for this g's m_1, m_2, m_3
    __shared__ int  s_meta[2];       // [0] = packed init counters, [1] = m0

    // Pack this g's 16 param rows via ballot: warp w -> rows 2w, 2w+1.
    const int* prow = params + (size_t)g * (T_DIM * P_DIM);
    #pragma unroll
    for (int r = 0; r < 2; r++) {
        int row = warp * 2 + r;
        u32 lo = __ballot_sync(0xffffffffu, prow[row * 64 + lane] & 1);
        u32 hi = __ballot_sync(0xffffffffu, prow[row * 64 + 32 + lane] & 1);
        if (lane == 0) { s_term[row].x = (int)lo; s_term[row].y = (int)hi; }
    }

    // Warp 0: per-term constants + class metadata + table-row staging.
    if (warp == 0) {
        int c = counts[g];
        c = c < 0 ? 0 : (c > T_DIM ? T_DIM : c);
        u32 vm = (c >= 16) ? 0xFFFFu : ((1u << c) - 1u);

        int p  = (lane < 16) ? (phases[g * T_DIM + lane] & 7) : 0;
        int k  = p & 3;
        int sg = (p >> 2) & 1;

        u32 b0m = __ballot_sync(0xffffffffu, k == 0) & vm;
        u32 b1m = __ballot_sync(0xffffffffu, k == 1) & vm;
        u32 b2m = __ballot_sync(0xffffffffu, k == 2) & vm;
        u32 b3m = __ballot_sync(0xffffffffu, k == 3) & vm;
        u32 sgm = __ballot_sync(0xffffffffu, sg == 1) & vm;

        int m0 = __popc(b0m), m1 = __popc(b1m), m2 = __popc(b2m), m3 = __popc(b3m);
        int s0 = __popc(b0m & sgm), s1 = __popc(b1m & sgm),
            s2 = __popc(b2m & sgm), s3 = __popc(b3m & sgm);

        if (lane < 16) {
            int valid = (vm >> lane) & 1;
            int pw = valid ? (sg ? -(1 << (8 * k)) : (1 << (8 * k))) : 0;
            s_term[lane].z = pw;
        }
        if (lane == 0) {
            s_meta[0] = s0 | (s1 << 8) | (s2 << 16) | (s3 << 24);
            s_meta[1] = m0;
        }
        // Stage table rows: entry b of class k -> g_T[k][(m_k - b)*17 + b]
        if (lane < 17) {
            if (lane <= m1) s_T[lane]      = g_T[0 * 289 + (m1 - lane) * 17 + lane];
            if (lane <= m2) s_T[17 + lane] = g_T[1 * 289 + (m2 - lane) * 17 + lane];
            if (lane <= m3) s_T[34 + lane] = g_T[2 * 289 + (m3 - lane) * 17 + lane];
        }
    }
    __syncthreads();

    const u64 v = pv[tid];
    const u32 vlo = (u32)v, vhi = (u32)(v >> 32);

    int cp = s_meta[0];
    const int m0 = s_meta[1];

    #pragma unroll
    for (int t = 0; t < T_DIM; t++) {
        int4 tw = s_term[t];
        u32 x = ((u32)tw.x & vlo) ^ ((u32)tw.y & vhi);
        cp += (int)(__popc(x) & 1u) * tw.z;     // IMAD into packed byte counters
    }

    int b0 = cp & 255;
    int b1 = (cp >> 8) & 255;
    int b2 = (cp >> 16) & 255;
    int b3 = (cp >> 24) & 255;

    int4 A = s_T[b1];
    int4 B = s_T[17 + b2];
    int4 C = s_T[34 + b3];

    int r0 = A.x*B.x - A.y*B.w - A.z*B.z - A.w*B.y;
    int r1 = A.x*B.y + A.y*B.x - A.z*B.w - A.w*B.z;
    int r2 = A.x*B.z + A.y*B.y + A.z*B.x - A.w*B.w;
    int r3 = A.x*B.w + A.y*B.z + A.z*B.y + A.w*B.x;

    int z0 = r0*C.x - r1*C.w - r2*C.z - r3*C.y;
    int z1 = r0*C.y + r1*C.x - r2*C.w - r3*C.z;
    int z2 = r0*C.z + r1*C.y + r2*C.x - r3*C.w;
    int z3 = r0*C.w + r1*C.z + r2*C.y + r3*C.x;

    int sc = (b0 == 0) ? (1 << m0) : 0;

    float4* o = (float4*)(out + ((size_t)tid * G_DIM + g) * 4);
    *o = make_float4((float)(z0 * sc), (float)(z1 * sc),
                     (float)(z2 * sc), (float)(-z3 * sc));
}

// ---------------------------------------------------------------------------
// Launch. Inputs identified BY SIZE (ordering-proof):
//   phases 32768 | params 2097152 | counts 2048 | param_vals 16384 | opp 32
// ---------------------------------------------------------------------------
extern "C" void kernel_launch(void* const* d_in, const int* in_sizes, int n_in,
                              void* d_out, int out_size) {
    const int* phases = nullptr;
    const int* params = nullptr;
    const int* counts = nullptr;
    const int* param_vals = nullptr;

    for (int i = 0; i < n_in; i++) {
        switch (in_sizes[i]) {
            case G_DIM * T_DIM:         phases     = (const int*)d_in[i]; break;
            case G_DIM * T_DIM * P_DIM: params     = (const int*)d_in[i]; break;
            case G_DIM:                 counts     = (const int*)d_in[i]; break;
            case B_DIM * P_DIM:         param_vals = (const int*)d_in[i]; break;
            default: break;  // one_plus_phases (32 floats) — unused
        }
    }

    u64* pv;
    cudaGetSymbolAddress((void**)&pv, g_pv);

    init_kernel<<<33, 256>>>(param_vals, pv);
    nodephases_main_kernel<<<G_DIM, 256>>>(params, phases, counts, pv, (float*)d_out);
}

// round 6
// speedup vs baseline: 1.1358x; 1.1358x over previous
#include <cuda_runtime.h>
#include <cstdint>

typedef unsigned long long u64;
typedef unsigned int u32;

#define G_DIM 2048
#define T_DIM 16
#define B_DIM 256
#define P_DIM 64

// Scratch (device globals: no allocation allowed)
__device__ u64  g_pv[B_DIM];
__device__ int4 g_T[3 * 17 * 17];   // T[k][a][b] = (1+w^{k+1})^a (1-w^{k+1})^b, a+b<=16

// ---------------------------------------------------------------------------
// Ring multiply in basis (1, w, w^2, w^3), w^4 = -1.
// ---------------------------------------------------------------------------
__device__ __forceinline__ void ringmul(int* z, const int* x, const int* y) {
    z[0] = x[0]*y[0] - x[1]*y[3] - x[2]*y[2] - x[3]*y[1];
    z[1] = x[0]*y[1] + x[1]*y[0] - x[2]*y[3] - x[3]*y[2];
    z[2] = x[0]*y[2] + x[1]*y[1] + x[2]*y[0] - x[3]*y[3];
    z[3] = x[0]*y[3] + x[1]*y[2] + x[2]*y[1] + x[3]*y[0];
}

__device__ __forceinline__ void ringcpy(int* d, const int* s) {
    d[0] = s[0]; d[1] = s[1]; d[2] = s[2]; d[3] = s[3];
}

// acc = f^n by square-and-multiply (<= 5 squarings + 5 muls)
__device__ __forceinline__ void ringpow(int* acc, const int* f, int n) {
    int base[4], tmp[4];
    acc[0] = 1; acc[1] = 0; acc[2] = 0; acc[3] = 0;
    ringcpy(base, f);
    while (n) {
        if (n & 1) { ringmul(tmp, acc, base); ringcpy(acc, tmp); }
        n >>= 1;
        if (n) { ringmul(tmp, base, base); ringcpy(base, tmp); }
    }
}

// ---------------------------------------------------------------------------
// Init kernel. Blocks 0..3: one table entry per thread (867 entries).
// Blocks 4..35: pack param_vals rows (256 x 64 int32 0/1) into u64 bitsets.
// ---------------------------------------------------------------------------
__global__ void init_kernel(const int* __restrict__ param_vals, u64* __restrict__ pv) {
    if (blockIdx.x < 4) {
        int e = blockIdx.x * 256 + threadIdx.x;
        if (e < 3 * 289) {
            int k = e / 289, r = e % 289, a = r / 17, b = r % 17;
            int4 out;
            if (a + b > 16) {
                out = make_int4(0, 0, 0, 0);
            } else {
                int kk = k + 1;
                int fp[4] = {1, 0, 0, 0}; fp[kk] = 1;     // 1 + w^kk
                int fm[4] = {1, 0, 0, 0}; fm[kk] = -1;    // 1 - w^kk
                int pa[4], pb[4], acc[4];
                ringpow(pa, fp, a);
                ringpow(pb, fm, b);
                ringmul(acc, pa, pb);
                out = make_int4(acc[0], acc[1], acc[2], acc[3]);
            }
            g_T[e] = out;
        }
    } else {
        int row  = (blockIdx.x - 4) * 8 + (threadIdx.x >> 5);
        int lane = threadIdx.x & 31;
        if (row < B_DIM) {
            const int* base = param_vals + (size_t)row * P_DIM;
            u32 lo = __ballot_sync(0xffffffffu, base[lane] & 1);
            u32 hi = __ballot_sync(0xffffffffu, base[lane + 32] & 1);
            if (lane == 0) pv[row] = ((u64)hi << 32) | (u64)lo;
        }
    }
}

// ---------------------------------------------------------------------------
// Main kernel: one block per PAIR of g's (grid 1024 x 256 threads).
// Per (b,g): packed byte counters via 2 independent IMAD chains, then
// result = T1[b1]*T2[b2]*T3[b3] * ((b0==0) ? 2^m0 : 0).
// Output float32 (B, G, 4); reference basis (1,w,w^2,w^7): c3 = -z3.
// ---------------------------------------------------------------------------
__global__ void __launch_bounds__(256)
nodephases_main_kernel(const int* __restrict__ params,
                       const int* __restrict__ phases,
                       const int* __restrict__ counts,
                       const u64* __restrict__ pv,
                       float* __restrict__ out) {
    const int g0   = blockIdx.x * 2;
    const int tid  = threadIdx.x;
    const int lane = tid & 31;
    const int warp = tid >> 5;

    __shared__ int4 s_term[2][T_DIM];   // x = w_lo, y = w_hi, z = pw
    __shared__ int4 s_T[2][3 * 17];     // staged table rows per g
    __shared__ int  s_meta[2][2];       // [0]=packed init counters, [1]=m0

    // Pack 32 param rows (2 g's x 16 terms): warp w -> rows 4w..4w+3.
    #pragma unroll
    for (int rr = 0; rr < 4; rr++) {
        int r  = warp * 4 + rr;
        int gi = r >> 4;
        int t  = r & 15;
        const int* pr = params + ((size_t)(g0 + gi)) * (T_DIM * P_DIM) + t * P_DIM;
        u32 lo = __ballot_sync(0xffffffffu, pr[lane] & 1);
        u32 hi = __ballot_sync(0xffffffffu, pr[lane + 32] & 1);
        if (lane == 0) { s_term[gi][t].x = (int)lo; s_term[gi][t].y = (int)hi; }
    }

    // Meta + table staging: warp 0 -> g0, warp 1 -> g0+1.
    if (warp < 2) {
        const int gi = warp;
        const int g  = g0 + gi;
        int c = counts[g];
        c = c < 0 ? 0 : (c > T_DIM ? T_DIM : c);
        u32 vm = (c >= 16) ? 0xFFFFu : ((1u << c) - 1u);

        int p  = (lane < 16) ? (phases[g * T_DIM + lane] & 7) : 0;
        int k  = p & 3;
        int sg = (p >> 2) & 1;

        u32 b0m = __ballot_sync(0xffffffffu, k == 0) & vm;
        u32 b1m = __ballot_sync(0xffffffffu, k == 1) & vm;
        u32 b2m = __ballot_sync(0xffffffffu, k == 2) & vm;
        u32 b3m = __ballot_sync(0xffffffffu, k == 3) & vm;
        u32 sgm = __ballot_sync(0xffffffffu, sg == 1) & vm;

        int m0 = __popc(b0m), m1 = __popc(b1m), m2 = __popc(b2m), m3 = __popc(b3m);
        int s0 = __popc(b0m & sgm), s1 = __popc(b1m & sgm),
            s2 = __popc(b2m & sgm), s3 = __popc(b3m & sgm);

        if (lane < 16) {
            int valid = (vm >> lane) & 1;
            s_term[gi][lane].z = valid ? (sg ? -(1 << (8 * k)) : (1 << (8 * k))) : 0;
        }
        if (lane == 0) {
            s_meta[gi][0] = s0 | (s1 << 8) | (s2 << 16) | (s3 << 24);
            s_meta[gi][1] = m0;
        }
        if (lane < 17) {
            if (lane <= m1) s_T[gi][lane]      = g_T[0 * 289 + (m1 - lane) * 17 + lane];
            if (lane <= m2) s_T[gi][17 + lane] = g_T[1 * 289 + (m2 - lane) * 17 + lane];
            if (lane <= m3) s_T[gi][34 + lane] = g_T[2 * 289 + (m3 - lane) * 17 + lane];
        }
    }
    __syncthreads();

    const u64 v = pv[tid];
    const u32 vlo = (u32)v, vhi = (u32)(v >> 32);

    float4* ob = (float4*)out + (size_t)tid * G_DIM + g0;

    #pragma unroll
    for (int gi = 0; gi < 2; gi++) {
        // Two independent accumulator chains; cpB biased to keep bytes >= 0.
        int cpA = s_meta[gi][0];
        int cpB = 0x10101010;
        #pragma unroll
        for (int t = 0; t < 8; t++) {
            int4 tw = s_term[gi][t];
            u32 x = ((u32)tw.x & vlo) ^ ((u32)tw.y & vhi);
            cpA += (int)(__popc(x) & 1u) * tw.z;
        }
        #pragma unroll
        for (int t = 8; t < 16; t++) {
            int4 tw = s_term[gi][t];
            u32 x = ((u32)tw.x & vlo) ^ ((u32)tw.y & vhi);
            cpB += (int)(__popc(x) & 1u) * tw.z;
        }
        int cp = cpA + cpB - 0x10101010;

        int b0 = cp & 255;
        int b1 = (cp >> 8) & 255;
        int b2 = (cp >> 16) & 255;
        int b3 = (cp >> 24) & 255;

        int4 A = s_T[gi][b1];
        int4 B = s_T[gi][17 + b2];
        int4 C = s_T[gi][34 + b3];

        int r0 = A.x*B.x - A.y*B.w - A.z*B.z - A.w*B.y;
        int r1 = A.x*B.y + A.y*B.x - A.z*B.w - A.w*B.z;
        int r2 = A.x*B.z + A.y*B.y + A.z*B.x - A.w*B.w;
        int r3 = A.x*B.w + A.y*B.z + A.z*B.y + A.w*B.x;

        int z0 = r0*C.x - r1*C.w - r2*C.z - r3*C.y;
        int z1 = r0*C.y + r1*C.x - r2*C.w - r3*C.z;
        int z2 = r0*C.z + r1*C.y + r2*C.x - r3*C.w;
        int z3 = r0*C.w + r1*C.z + r2*C.y + r3*C.x;

        int sc = (b0 == 0) ? (1 << s_meta[gi][1]) : 0;

        ob[gi] = make_float4((float)(z0 * sc), (float)(z1 * sc),
                             (float)(z2 * sc), (float)(-z3 * sc));
    }
}

// ---------------------------------------------------------------------------
// Launch. Inputs identified BY SIZE (ordering-proof):
//   phases 32768 | params 2097152 | counts 2048 | param_vals 16384 | opp 32
// ---------------------------------------------------------------------------
extern "C" void kernel_launch(void* const* d_in, const int* in_sizes, int n_in,
                              void* d_out, int out_size) {
    const int* phases = nullptr;
    const int* params = nullptr;
    const int* counts = nullptr;
    const int* param_vals = nullptr;

    for (int i = 0; i < n_in; i++) {
        switch (in_sizes[i]) {
            case G_DIM * T_DIM:         phases     = (const int*)d_in[i]; break;
            case G_DIM * T_DIM * P_DIM: params     = (const int*)d_in[i]; break;
            case G_DIM:                 counts     = (const int*)d_in[i]; break;
            case B_DIM * P_DIM:         param_vals = (const int*)d_in[i]; break;
            default: break;  // one_plus_phases (32 floats) — unused
        }
    }

    u64* pv;
    cudaGetSymbolAddress((void**)&pv, g_pv);

    init_kernel<<<36, 256>>>(param_vals, pv);
    nodephases_main_kernel<<<G_DIM / 2, 256>>>(params, phases, counts, pv, (float*)d_out);
}